// round 14
// baseline (speedup 1.0000x reference)
#include <cuda_runtime.h>
#include <mma.h>
#include <cstdint>

#define N_NODES 100000
#define N_EDGES 1600000
#define D 64
#define SCAN_NB 391   // 391*256 = 100096 >= N_NODES
#define NTILES 782    // 782*128 = 100096 >= N_NODES
#define ULD 132       // padded leading dim for U / B tiles (floats)
#define OLD 68        // padded leading dim for output staging

using namespace nvcuda;

// Scratch (static __device__ — allocation-free per harness rules)
__device__ int   g_is64;
__device__ int   g_deg[N_NODES];
__device__ int   g_rowoff[N_NODES + 1];
__device__ int   g_cursor[N_NODES];
__device__ float g_dinv[N_NODES];
__device__ int   g_srcidx[N_EDGES];
__device__ int   g_bsum[512];
__device__ float g_A[N_NODES * D];   // aggregated (mean) neighbor feats
__device__ float g_H[N_NODES * D];   // layer-1 hidden

__device__ __forceinline__ int clampN(int v) {
    return min(max(v, 0), N_NODES - 1);
}
__device__ __forceinline__ int load_id(const void* ei, long long idx, int is64) {
    int v = is64 ? (int)((const long long*)ei)[idx] : ((const int*)ei)[idx];
    return clampN(v);
}

// ---------- init: zero degrees + dtype detect ----------
__global__ void k_init(const int* __restrict__ ei32) {
    int i = blockIdx.x * blockDim.x + threadIdx.x;
    if (i < N_NODES) g_deg[i] = 0;
    if (i == 0) {
        int odd_zero = 1;
#pragma unroll
        for (int j = 1; j < 64; j += 2)
            if (ei32[j] != 0) odd_zero = 0;
        g_is64 = odd_zero;
    }
}

__global__ void k_hist(const void* __restrict__ ei) {
    int e = blockIdx.x * blockDim.x + threadIdx.x;
    if (e < N_EDGES) {
        int is64 = g_is64;
        int dst = load_id(ei, (long long)N_EDGES + e, is64);
        atomicAdd(&g_deg[dst], 1);
    }
}

__global__ void k_scan1() {
    __shared__ int sh[256];
    int i = blockIdx.x * 256 + threadIdx.x;
    int t = threadIdx.x;
    sh[t] = (i < N_NODES) ? g_deg[i] : 0;
    __syncthreads();
    for (int off = 128; off > 0; off >>= 1) {
        if (t < off) sh[t] += sh[t + off];
        __syncthreads();
    }
    if (t == 0) g_bsum[blockIdx.x] = sh[0];
}

__global__ void k_scan23() {
    __shared__ int sb2[512];
    __shared__ int sh[256];
    int b = blockIdx.x;
    int t = threadIdx.x;
    sb2[t]       = (t < SCAN_NB) ? g_bsum[t] : 0;
    sb2[t + 256] = (t + 256 < SCAN_NB) ? g_bsum[t + 256] : 0;
    __syncthreads();
    for (int off = 1; off < 512; off <<= 1) {
        int v0 = (t >= off) ? sb2[t - off] : 0;
        int v1 = (t + 256 >= off) ? sb2[t + 256 - off] : 0;
        __syncthreads();
        sb2[t] += v0;
        sb2[t + 256] += v1;
        __syncthreads();
    }
    int boff = (b == 0) ? 0 : sb2[b - 1];
    int i = b * 256 + t;
    int d = (i < N_NODES) ? g_deg[i] : 0;
    sh[t] = d;
    __syncthreads();
    for (int off = 1; off < 256; off <<= 1) {
        int v = (t >= off) ? sh[t - off] : 0;
        __syncthreads();
        sh[t] += v;
        __syncthreads();
    }
    if (i < N_NODES) {
        int excl = sh[t] - d + boff;
        g_rowoff[i] = excl;
        g_cursor[i] = excl;
        g_dinv[i] = 1.0f / (float)max(d, 1);
    }
    if (i == 0) g_rowoff[N_NODES] = N_EDGES;
}

__global__ void k_fill(const void* __restrict__ ei) {
    int e = blockIdx.x * blockDim.x + threadIdx.x;
    if (e < N_EDGES) {
        int is64 = g_is64;
        int dst = load_id(ei, (long long)N_EDGES + e, is64);
        int src = load_id(ei, e, is64);
        int pos = atomicAdd(&g_cursor[dst], 1);
        pos = min(max(pos, 0), N_EDGES - 1);
        g_srcidx[pos] = src;
    }
}

// ---------- mean aggregation: warp/node, half-warp per edge, float4 lanes ----
// lanes 0-15 process even edges, 16-31 odd edges; one LDG.128 covers 2 edges.
template <bool FIRST>
__global__ void k_agg(const float* __restrict__ xext) {
    const float* __restrict__ feat = FIRST ? xext : (const float*)g_H;
    int gw = (blockIdx.x * blockDim.x + threadIdx.x) >> 5;
    int lane = threadIdx.x & 31;
    if (gw >= N_NODES) return;
    int s = g_rowoff[gw], e = g_rowoff[gw + 1];
    int half = lane >> 4;       // 0: edge i, 1: edge i+1
    int hl = lane & 15;         // float4 index within row
    float ax = 0.f, ay = 0.f, az = 0.f, aw = 0.f;
    int i = s;
    for (; i + 7 < e; i += 8) {   // 4 gathers in flight, 8 edges
        int i0 = g_srcidx[i + half];
        int i1 = g_srcidx[i + 2 + half];
        int i2 = g_srcidx[i + 4 + half];
        int i3 = g_srcidx[i + 6 + half];
        float4 v0 = ((const float4*)&feat[i0 << 6])[hl];
        float4 v1 = ((const float4*)&feat[i1 << 6])[hl];
        float4 v2 = ((const float4*)&feat[i2 << 6])[hl];
        float4 v3 = ((const float4*)&feat[i3 << 6])[hl];
        ax += v0.x + v1.x + v2.x + v3.x;
        ay += v0.y + v1.y + v2.y + v3.y;
        az += v0.z + v1.z + v2.z + v3.z;
        aw += v0.w + v1.w + v2.w + v3.w;
    }
    for (; i + 1 < e; i += 2) {
        int i0 = g_srcidx[i + half];
        float4 v = ((const float4*)&feat[i0 << 6])[hl];
        ax += v.x; ay += v.y; az += v.z; aw += v.w;
    }
    if (i < e && half == 0) {    // final odd edge: half 0 only
        int i0 = g_srcidx[i];
        float4 v = ((const float4*)&feat[i0 << 6])[hl];
        ax += v.x; ay += v.y; az += v.z; aw += v.w;
    }
    // combine the two half-warp accumulators (same hl, other half)
    ax += __shfl_xor_sync(0xFFFFFFFFu, ax, 16);
    ay += __shfl_xor_sync(0xFFFFFFFFu, ay, 16);
    az += __shfl_xor_sync(0xFFFFFFFFu, az, 16);
    aw += __shfl_xor_sync(0xFFFFFFFFu, aw, 16);
    if (half == 0) {
        float di = g_dinv[gw];
        ((float4*)&g_A[gw << 6])[hl] =
            make_float4(ax * di, ay * di, az * di, aw * di);
    }
}

// ---------- wmma tf32 dense: out = [A|X] @ [Wl|Wr]^T + b (+relu) ----------
// 256 threads (8 warps x 16-row stripes). dyn smem: sU[128*ULD] | sB[64*ULD]
#define DSM_TOTAL ((128 * ULD + 64 * ULD) * 4)

template <bool FIRST>
__global__ void __launch_bounds__(256)
k_denseT(const float* __restrict__ xext,
         const float* __restrict__ Wl, const float* __restrict__ bias,
         const float* __restrict__ Wr, float* __restrict__ outext) {
    extern __shared__ float dsm[];
    float* sU = dsm;                  // [128][ULD] tf32 (row-major)
    float* sB = dsm + 128 * ULD;      // [64][ULD]  Wc[n][k]
    __shared__ float s_bias[64];

    const float* __restrict__ X = FIRST ? xext : (const float*)g_H;
    float* out = FIRST ? (float*)g_H : outext;

    int tid = threadIdx.x;
    int wid = tid >> 5;
    if (tid < 64) s_bias[tid] = bias[tid];

    // fill U: thread t -> row t>>1; part t&1 (0: A cols 0-63, 1: X cols 64-127)
    {
        int row = tid >> 1, part = tid & 1;
        int node = clampN(blockIdx.x * 128 + row);
        const float4* src = part ? (const float4*)(X + node * D)
                                 : (const float4*)(g_A + node * D);
        float* ur = sU + row * ULD + part * 64;
#pragma unroll
        for (int q = 0; q < 16; q++) {
            float4 v = src[q];
            ur[4 * q]     = wmma::__float_to_tf32(v.x);
            ur[4 * q + 1] = wmma::__float_to_tf32(v.y);
            ur[4 * q + 2] = wmma::__float_to_tf32(v.z);
            ur[4 * q + 3] = wmma::__float_to_tf32(v.w);
        }
    }
    // fill B: sB[n][k]; k<64 -> Wl[n][k], else Wr[n][k-64]
    for (int idx = tid; idx < 64 * 128; idx += 256) {
        int n = idx >> 7, k = idx & 127;
        float w = (k < 64) ? Wl[n * 64 + k] : Wr[n * 64 + (k - 64)];
        sB[n * ULD + k] = wmma::__float_to_tf32(w);
    }
    __syncthreads();

    // warp wid: rows [wid*16, wid*16+16), all 64 cols
    wmma::fragment<wmma::accumulator, 16, 16, 8, float> acc[4];
#pragma unroll
    for (int nt = 0; nt < 4; nt++) wmma::fill_fragment(acc[nt], 0.0f);

    int m0 = wid * 16;
#pragma unroll 1
    for (int k = 0; k < 128; k += 8) {
        wmma::fragment<wmma::matrix_a, 16, 16, 8, wmma::precision::tf32,
                       wmma::row_major> fa;
        wmma::load_matrix_sync(fa, sU + m0 * ULD + k, ULD);
#pragma unroll
        for (int nt = 0; nt < 4; nt++) {
            wmma::fragment<wmma::matrix_b, 16, 16, 8, wmma::precision::tf32,
                           wmma::col_major> fb;
            wmma::load_matrix_sync(fb, sB + (nt * 16) * ULD + k, ULD);
            wmma::mma_sync(acc[nt], fa, fb, acc[nt]);
        }
    }

    __syncthreads();   // warps done reading sU; reuse as output staging
    float* sO = sU;    // [128][OLD]
#pragma unroll
    for (int nt = 0; nt < 4; nt++)
        wmma::store_matrix_sync(sO + m0 * OLD + nt * 16, acc[nt], OLD,
                                wmma::mem_row_major);
    __syncthreads();

    // epilogue: thread t -> row t>>1, col half (t&1)*32
    {
        int row = tid >> 1, coff = (tid & 1) * 32;
        int onode = blockIdx.x * 128 + row;
        if (onode < N_NODES) {
            const float* r = sO + row * OLD + coff;
            float4* o = (float4*)(out + onode * D + coff);
#pragma unroll
            for (int q = 0; q < 8; q++) {
                float r0 = r[4 * q]     + s_bias[coff + 4 * q];
                float r1 = r[4 * q + 1] + s_bias[coff + 4 * q + 1];
                float r2 = r[4 * q + 2] + s_bias[coff + 4 * q + 2];
                float r3 = r[4 * q + 3] + s_bias[coff + 4 * q + 3];
                if (FIRST) {
                    r0 = fmaxf(r0, 0.f); r1 = fmaxf(r1, 0.f);
                    r2 = fmaxf(r2, 0.f); r3 = fmaxf(r3, 0.f);
                }
                o[q] = make_float4(r0, r1, r2, r3);
            }
        }
    }
}

extern "C" void kernel_launch(void* const* d_in, const int* in_sizes, int n_in,
                              void* d_out, int out_size) {
    const float* x   = (const float*)d_in[0];
    const void*  ei  = d_in[1];
    const float* W1l = (const float*)d_in[2];
    const float* b1  = (const float*)d_in[3];
    const float* W1r = (const float*)d_in[4];
    const float* W2l = (const float*)d_in[5];
    const float* b2  = (const float*)d_in[6];
    const float* W2r = (const float*)d_in[7];
    float* out = (float*)d_out;

    static int s_attr = 0;
    if (!s_attr) {
        cudaFuncSetAttribute(k_denseT<true>,
            cudaFuncAttributeMaxDynamicSharedMemorySize, DSM_TOTAL);
        cudaFuncSetAttribute(k_denseT<false>,
            cudaFuncAttributeMaxDynamicSharedMemorySize, DSM_TOTAL);
        s_attr = 1;
    }

    k_init<<<SCAN_NB, 256>>>((const int*)ei);
    k_hist<<<(N_EDGES + 255) / 256, 256>>>(ei);
    k_scan1<<<SCAN_NB, 256>>>();
    k_scan23<<<SCAN_NB, 256>>>();
    k_fill<<<(N_EDGES + 255) / 256, 256>>>(ei);

    // Layer 1
    k_agg<true><<<(N_NODES * 32 + 255) / 256, 256>>>(x);
    k_denseT<true><<<NTILES, 256, DSM_TOTAL>>>(x, W1l, b1, W1r, nullptr);

    // Layer 2
    k_agg<false><<<(N_NODES * 32 + 255) / 256, 256>>>(x);
    k_denseT<false><<<NTILES, 256, DSM_TOTAL>>>(x, W2l, b2, W2r, out);
}